// round 16
// baseline (speedup 1.0000x reference)
#include <cuda_runtime.h>
#include <cuda_fp16.h>
#include <cstdint>

// Problem constants (B=4, S=2048 -> T=8192; D=512, H=2048, E=8, K=2)
#define T_TOK 8192
#define DIM   512
#define HID   2048
#define NE    8
#define TILE_M 128
#define MAXROWS (T_TOK*2 + NE*TILE_M)   // 17408
#define MAXT    (MAXROWS/TILE_M)        // 136

#define BM 128
#define BN 128
#define BK 64
#define NTHREADS 256
#define NSTAGE 3
#define A_BYTES (BM*BK*2)               // 16384
#define B_BYTES (BK*BN*2)               // 16384
#define STAGE_B (A_BYTES + B_BYTES)     // 32768
#define SM_BYTES (NSTAGE*STAGE_B)       // 98304

#define G1_BLKS (MAXT*16)               // 2176
#define G2_BLKS (MAXT*4)                // 544
#define G1_THREADS (G1_BLKS*NTHREADS)   // 557056

// ---------------- device scratch ----------------
__device__ int   g_cnt[NE];
__device__ int   g_tok[NE*T_TOK];
__device__ float g_wt [NE*T_TOK];
__device__ int   g_tile_done[MAXT];
__device__ int   g_prol_done;
__device__ __half g_xh [(size_t)T_TOK*DIM];
__device__ __half g_w1h[(size_t)NE*DIM*HID];
__device__ __half g_w2h[(size_t)NE*HID*DIM];
__device__ __half g_h  [(size_t)MAXROWS*HID];

// ---------------- helpers ----------------
__device__ __forceinline__ float gelu_exact(float v) {
    return 0.5f * v * (1.0f + erff(v * 0.70710678118654752f));
}
__device__ __forceinline__ uint32_t smem_u32(const void* p) {
    uint32_t a; asm("{ .reg .u64 t; cvta.to.shared.u64 t, %1; cvt.u32.u64 %0, t; }" : "=r"(a) : "l"(p));
    return a;
}
__device__ __forceinline__ void cp16(uint32_t d, const void* s) {
    asm volatile("cp.async.cg.shared.global [%0], [%1], 16;" :: "r"(d), "l"(s));
}
#define CP_COMMIT() asm volatile("cp.async.commit_group;" ::: "memory")
#define CP_WAIT1()  asm volatile("cp.async.wait_group 1;" ::: "memory")
#define CP_WAIT0()  asm volatile("cp.async.wait_group 0;" ::: "memory")

#define LDSM4(r, addr) \
    asm volatile("ldmatrix.sync.aligned.m8n8.x4.shared.b16 {%0,%1,%2,%3}, [%4];" \
        : "=r"((r)[0]), "=r"((r)[1]), "=r"((r)[2]), "=r"((r)[3]) : "r"(addr))
#define LDSM4T(r0,r1,r2,r3, addr) \
    asm volatile("ldmatrix.sync.aligned.m8n8.x4.trans.shared.b16 {%0,%1,%2,%3}, [%4];" \
        : "=r"(r0), "=r"(r1), "=r"(r2), "=r"(r3) : "r"(addr))
#define MMA16816(c, a, b) \
    asm volatile("mma.sync.aligned.m16n8k16.row.col.f32.f16.f16.f32 " \
        "{%0,%1,%2,%3}, {%4,%5,%6,%7}, {%8,%9}, {%0,%1,%2,%3};" \
        : "+f"((c)[0]), "+f"((c)[1]), "+f"((c)[2]), "+f"((c)[3]) \
        : "r"((a)[0]), "r"((a)[1]), "r"((a)[2]), "r"((a)[3]), "r"((b)[0]), "r"((b)[1]))

// ---------------- kernel 0: w1 -> fp16 convert + flag/counter reset ---------
__global__ __launch_bounds__(256) void cvt_w1_kernel(const float* __restrict__ w1)
{
    if (blockIdx.x == 0) {
        if (threadIdx.x < NE) g_cnt[threadIdx.x] = 0;
        if (threadIdx.x < MAXT) g_tile_done[threadIdx.x] = 0;
        if (threadIdx.x == 200) g_prol_done = 0;
    }
    const int nq = NE*DIM*HID/4/4;   // 524288 quarter-span in float4s
    int i = blockIdx.x * blockDim.x + threadIdx.x;
#pragma unroll
    for (int r = 0; r < 4; r++) {
        int j = i + r*nq;
        float4 a = ((const float4*)w1)[j];
        __half2* d = (__half2*)(g_w1h + (size_t)j*4);
        d[0] = __floats2half2_rn(a.x, a.y);
        d[1] = __floats2half2_rn(a.z, a.w);
    }
}

// ---------------- kernel 1: router (+ fused x -> fp16) ----------------
__global__ __launch_bounds__(256) void router_kernel(
    const float* __restrict__ x, const float* __restrict__ rw,
    const float* __restrict__ rb, float* __restrict__ logits_out, int write_logits)
{
    __shared__ float sw[NE*DIM];
    __shared__ float sb[NE];
    for (int i = threadIdx.x; i < NE*DIM; i += 256) sw[i] = rw[i];
    if (threadIdx.x < NE) sb[threadIdx.x] = rb[threadIdx.x];
    __syncthreads();

    int warp = threadIdx.x >> 5, lane = threadIdx.x & 31;
    int t = blockIdx.x * 8 + warp;
    if (t >= T_TOK) return;

    float acc[NE];
#pragma unroll
    for (int e = 0; e < NE; e++) acc[e] = 0.f;

    const float* xr = x + (size_t)t * DIM;
    __half* xh = g_xh + (size_t)t * DIM;
#pragma unroll
    for (int it = 0; it < DIM/64; it++) {
        int d = it*64 + lane*2;
        float2 v = *(const float2*)(xr + d);
        *(__half2*)(xh + d) = __floats2half2_rn(v.x, v.y);
#pragma unroll
        for (int e = 0; e < NE; e++)
            acc[e] += v.x * sw[e*DIM + d] + v.y * sw[e*DIM + d + 1];
    }
#pragma unroll
    for (int e = 0; e < NE; e++) {
#pragma unroll
        for (int off = 16; off > 0; off >>= 1)
            acc[e] += __shfl_xor_sync(0xffffffffu, acc[e], off);
        acc[e] += sb[e];
    }

    if (lane == 0) {
        if (write_logits) {
#pragma unroll
            for (int e = 0; e < NE; e++) logits_out[(size_t)t*NE + e] = acc[e];
        }
        int i0 = 0; float v0 = acc[0];
#pragma unroll
        for (int e = 1; e < NE; e++) if (acc[e] > v0) { v0 = acc[e]; i0 = e; }
        int i1 = -1; float v1 = -1e30f;
#pragma unroll
        for (int e = 0; e < NE; e++) if (e != i0 && acc[e] > v1) { v1 = acc[e]; i1 = e; }
        float ex = expf(v1 - v0);
        float w0 = 1.f / (1.f + ex);
        float w1v = 1.f - w0;

        int s0 = atomicAdd(&g_cnt[i0], 1);
        g_tok[i0*T_TOK + s0] = t; g_wt[i0*T_TOK + s0] = w0;
        int s1 = atomicAdd(&g_cnt[i1], 1);
        g_tok[i1*T_TOK + s1] = t; g_wt[i1*T_TOK + s1] = w1v;
    }
}

// ---------------- tile derivation from g_cnt ----------------
__device__ __forceinline__ bool derive_tile(int tile, int& e, int& slot0, int& grow0, int& cnt)
{
    int t = tile, grow = 0;
    int ee = 0;
#pragma unroll
    for (ee = 0; ee < NE; ee++) {
        int c = __ldg(&g_cnt[ee]);
        int tl = (c + TILE_M - 1) >> 7;
        if (t < tl) break;
        t -= tl; grow += tl * TILE_M;
    }
    if (ee == NE) return false;
    e = ee; slot0 = t * TILE_M; grow0 = grow + t * TILE_M;
    cnt = __ldg(&g_cnt[e]);
    return true;
}

// ---------------- shared GEMM tile body (R11/R15 mainloop, known good) ------
// FIRST:  A = gathered g_xh rows (K=512),  B = g_w1h, out = fp16 gelu(.+b1) -> g_h
// !FIRST: A = g_h rows (K=2048),           B = g_w2h, out: atomicAdd (.+b2)*wt -> out
template<bool FIRST>
__device__ __forceinline__ void gemm_tile(
    int e, int slot0, int grow0, int cnt, int n0,
    const float* __restrict__ bias, float* __restrict__ out,
    char* smem, int tid)
{
    constexpr int KEXT = FIRST ? DIM : HID;
    constexpr int NTOT = FIRST ? HID : DIM;
    constexpr int NS   = KEXT / BK;

    __shared__ float s_wt[BM];
    __shared__ int   s_tok[BM];

    int warp = tid >> 5, lane = tid & 31;
    int wm = warp & 1, wn = warp >> 1;      // 2 x 4 warp grid, 64x32 per warp

    const __half* aptr[4];
    {
#pragma unroll
        for (int it = 0; it < 4; it++) {
            int row = (tid >> 3) + it*32;
            if (FIRST) {
                int sl = slot0 + row;
                int tok = (sl < cnt) ? g_tok[e*T_TOK + sl] : 0;
                aptr[it] = g_xh + (size_t)tok*DIM + (tid & 7)*8;
            } else {
                aptr[it] = g_h + (size_t)(grow0 + row)*HID + (tid & 7)*8;
            }
        }
        if (!FIRST && tid < BM) {
            int sl = slot0 + tid;
            bool valid = sl < cnt;
            s_wt[tid]  = valid ? g_wt[e*T_TOK + sl] : 0.f;
            s_tok[tid] = valid ? g_tok[e*T_TOK + sl] : -1;
        }
    }
    const __half* Wbase = (FIRST ? g_w1h : g_w2h) + (size_t)e*KEXT*NTOT + n0;

    uint32_t sm_u = smem_u32(smem);
    uint32_t a_dst[4], b_dst[4];
    const __half* bsrc[4];
    {
        int c = tid & 7, row0 = tid >> 3;
#pragma unroll
        for (int it = 0; it < 4; it++) {
            int row = row0 + it*32;
            a_dst[it] = row*128 + ((c ^ (row & 7))*16);
        }
        int bc = tid & 15, k0 = tid >> 4;
#pragma unroll
        for (int it = 0; it < 4; it++) {
            int k = k0 + it*16;
            b_dst[it] = A_BYTES + k*256 + (((bc ^ (k & 7)) & 15)*16);
            bsrc[it]  = Wbase + (size_t)k*NTOT + bc*8;
        }
    }

    float c[4][4][4];
#pragma unroll
    for (int mf = 0; mf < 4; mf++)
#pragma unroll
        for (int nf = 0; nf < 4; nf++)
#pragma unroll
            for (int r = 0; r < 4; r++) c[mf][nf][r] = 0.f;

    auto load_stage = [&](int s) {
        uint32_t st = sm_u + (s % NSTAGE)*STAGE_B;
#pragma unroll
        for (int it = 0; it < 4; it++)
            cp16(st + a_dst[it], aptr[it] + s*BK);
#pragma unroll
        for (int it = 0; it < 4; it++)
            cp16(st + b_dst[it], bsrc[it] + (size_t)s*BK*NTOT);
    };

    load_stage(0); CP_COMMIT();
    load_stage(1); CP_COMMIT();

    for (int s = 0; s < NS; s++) {
        CP_WAIT1();
        __syncthreads();

        uint32_t stA = sm_u + (s % NSTAGE)*STAGE_B;
        uint32_t stB = stA + A_BYTES;
#pragma unroll
        for (int ks = 0; ks < BK/16; ks++) {
            uint32_t a0[2][4];
#pragma unroll
            for (int mf = 0; mf < 2; mf++) {
                int row = wm*64 + mf*16 + (lane & 15);
                int kc  = ks*16 + (lane >> 4)*8;
                uint32_t ad = stA + row*128 + (((kc >> 3) ^ (row & 7))*16);
                LDSM4(a0[mf], ad);
            }
            uint32_t b[4][2];
#pragma unroll
            for (int p = 0; p < 2; p++) {
                int k = ks*16 + (lane & 15);
                int n = wn*32 + p*16 + (lane >> 4)*8;
                uint32_t bd = stB + k*256 + ((((n >> 3) ^ (k & 7)) & 15)*16);
                uint32_t r0, r1, r2, r3;
                LDSM4T(r0, r1, r2, r3, bd);
                b[2*p  ][0] = r0; b[2*p  ][1] = r1;
                b[2*p+1][0] = r2; b[2*p+1][1] = r3;
            }
            uint32_t a1[2][4];
#pragma unroll
            for (int mf = 0; mf < 2; mf++) {
                int row = wm*64 + (mf+2)*16 + (lane & 15);
                int kc  = ks*16 + (lane >> 4)*8;
                uint32_t ad = stA + row*128 + (((kc >> 3) ^ (row & 7))*16);
                LDSM4(a1[mf], ad);
            }
#pragma unroll
            for (int mf = 0; mf < 2; mf++)
#pragma unroll
                for (int nf = 0; nf < 4; nf++)
                    MMA16816(c[mf][nf], a0[mf], b[nf]);

            if (ks == 0) {
                if (s + 2 < NS) load_stage(s + 2);
                CP_COMMIT();
            }

#pragma unroll
            for (int mf = 0; mf < 2; mf++)
#pragma unroll
                for (int nf = 0; nf < 4; nf++)
                    MMA16816(c[mf+2][nf], a1[mf], b[nf]);
        }
    }
    CP_WAIT0();

    // ---- epilogue ----
    {
        int g = lane >> 2, tq = lane & 3;
        const float* be = bias + (size_t)e*NTOT + n0;
        float bias0[4], bias1[4];
#pragma unroll
        for (int nf = 0; nf < 4; nf++) {
            int col = wn*32 + nf*8 + tq*2;
            bias0[nf] = be[col];
            bias1[nf] = be[col + 1];
        }
#pragma unroll
        for (int mf = 0; mf < 4; mf++) {
            int r0 = wm*64 + mf*16 + g;
            int r1 = r0 + 8;
            if (FIRST) {
                __half* o0 = g_h + (size_t)(grow0 + r0)*HID + n0;
                __half* o1 = g_h + (size_t)(grow0 + r1)*HID + n0;
#pragma unroll
                for (int nf = 0; nf < 4; nf++) {
                    int col = wn*32 + nf*8 + tq*2;
                    float v0 = gelu_exact(c[mf][nf][0] + bias0[nf]);
                    float v1 = gelu_exact(c[mf][nf][1] + bias1[nf]);
                    float v2 = gelu_exact(c[mf][nf][2] + bias0[nf]);
                    float v3 = gelu_exact(c[mf][nf][3] + bias1[nf]);
                    *(__half2*)(o0 + col) = __floats2half2_rn(v0, v1);
                    *(__half2*)(o1 + col) = __floats2half2_rn(v2, v3);
                }
            } else {
                float wt0 = s_wt[r0], wt1 = s_wt[r1];
                int  t0 = s_tok[r0], t1 = s_tok[r1];
                float* o0 = out + (size_t)(t0 < 0 ? 0 : t0)*NTOT + n0;
                float* o1 = out + (size_t)(t1 < 0 ? 0 : t1)*NTOT + n0;
#pragma unroll
                for (int nf = 0; nf < 4; nf++) {
                    int col = wn*32 + nf*8 + tq*2;
                    if (t0 >= 0) {
                        atomicAdd(o0 + col,     (c[mf][nf][0] + bias0[nf]) * wt0);
                        atomicAdd(o0 + col + 1, (c[mf][nf][1] + bias1[nf]) * wt0);
                    }
                    if (t1 >= 0) {
                        atomicAdd(o1 + col,     (c[mf][nf][2] + bias0[nf]) * wt1);
                        atomicAdd(o1 + col + 1, (c[mf][nf][3] + bias1[nf]) * wt1);
                    }
                }
            }
        }
    }
}

// ---------------- fused GEMM1 -> GEMM2 single kernel -----------------------
// Blocks [0, G1_BLKS): gemm1 (tile-major) + hidden side-work (zero out, cvt w2).
// Blocks [G1_BLKS, G1_BLKS+G2_BLKS): gemm2; spins until its tile's 16 gemm1
// blocks and all side-work prologues are done. Linear dispatch order makes
// this deadlock-free (all gemm1 blocks dispatched before any gemm2 starts).
__global__ __launch_bounds__(NTHREADS, 2) void fused_gemm_kernel(
    const float* __restrict__ b1, const float* __restrict__ b2,
    float* __restrict__ out, const float* __restrict__ w2src)
{
    extern __shared__ char smem[];
    int tid = threadIdx.x;
    int bid = blockIdx.x;

    if (bid < G1_BLKS) {
        // ---- side work: zero out region + cvt w2 (fire-and-forget) ----
        {
            unsigned lid = (unsigned)bid * NTHREADS + tid;
            float4 z; z.x = 0.f; z.y = 0.f; z.z = 0.f; z.w = 0.f;
#pragma unroll
            for (int r = 0; r < 2; r++) {
                unsigned j = lid + r * G1_THREADS;
                if (j < (unsigned)(T_TOK*DIM/4)) ((float4*)out)[j] = z;
            }
            const unsigned nh = NE*HID*DIM/4/2;
#pragma unroll
            for (int r = 0; r < 2; r++) {
                unsigned j = lid + r * G1_THREADS;
                if (j < nh) {
#pragma unroll
                    for (int h = 0; h < 2; h++) {
                        unsigned jj = j + h*nh;
                        float4 a = ((const float4*)w2src)[jj];
                        __half2* d = (__half2*)(g_w2h + (size_t)jj*4);
                        d[0] = __floats2half2_rn(a.x, a.y);
                        d[1] = __floats2half2_rn(a.z, a.w);
                    }
                }
            }
        }
        __threadfence();
        __syncthreads();
        if (tid == 0) atomicAdd(&g_prol_done, 1);

        int tile = bid >> 4;
        int n0   = (bid & 15) * BN;
        int e, slot0, grow0, cnt;
        if (derive_tile(tile, e, slot0, grow0, cnt))
            gemm_tile<true>(e, slot0, grow0, cnt, n0, b1, out, smem, tid);
        __threadfence();
        __syncthreads();
        if (tid == 0) atomicAdd(&g_tile_done[tile], 1);
    } else {
        int b2id = bid - G1_BLKS;
        int tile = b2id >> 2;
        int n0   = (b2id & 3) * BN;
        int e, slot0, grow0, cnt;
        if (!derive_tile(tile, e, slot0, grow0, cnt)) return;

        if (tid == 0) {
            while (*(volatile int*)&g_prol_done < G1_BLKS) __nanosleep(256);
            while (*(volatile int*)&g_tile_done[tile] < 16) __nanosleep(256);
            __threadfence();
        }
        __syncthreads();
        gemm_tile<false>(e, slot0, grow0, cnt, n0, b2, out, smem, tid);
    }
}

// ---------------- host entry ----------------
extern "C" void kernel_launch(void* const* d_in, const int* in_sizes, int n_in,
                              void* d_out, int out_size)
{
    const float* x   = (const float*)d_in[0];
    const float* rw  = (const float*)d_in[1];
    const float* rb  = (const float*)d_in[2];
    const float* w1  = (const float*)d_in[3];
    const float* b1  = (const float*)d_in[4];
    const float* w2  = (const float*)d_in[5];
    const float* b2  = (const float*)d_in[6];
    float* out = (float*)d_out;

    int write_logits = (out_size >= T_TOK*DIM + T_TOK*NE) ? 1 : 0;
    float* logits_out = out + (size_t)T_TOK*DIM;

    cudaFuncSetAttribute(fused_gemm_kernel,
                         cudaFuncAttributeMaxDynamicSharedMemorySize, SM_BYTES);

    cvt_w1_kernel<<<NE*DIM*HID/16/256, 256>>>(w1);                 // 2048 blocks
    router_kernel<<<T_TOK/8, 256>>>(x, rw, rb, logits_out, write_logits);
    fused_gemm_kernel<<<G1_BLKS + G2_BLKS, NTHREADS, SM_BYTES>>>(b1, b2, out, w2);
}

// round 17
// speedup vs baseline: 1.1438x; 1.1438x over previous
#include <cuda_runtime.h>
#include <cuda_fp16.h>
#include <cstdint>

// Problem constants (B=4, S=2048 -> T=8192; D=512, H=2048, E=8, K=2)
#define T_TOK 8192
#define DIM   512
#define HID   2048
#define NE    8
#define TILE_M 128
#define MAXROWS (T_TOK*2 + NE*TILE_M)   // 17408
#define MAXT    (MAXROWS/TILE_M)        // 136

#define BM 128
#define BN 128
#define BK 64
#define NTHREADS 256
#define NSTAGE 3
#define A_BYTES (BM*BK*2)               // 16384
#define B_BYTES (BK*BN*2)               // 16384
#define STAGE_B (A_BYTES + B_BYTES)     // 32768
#define SM_BYTES (NSTAGE*STAGE_B)       // 98304

// gemm1 grid = 136 x 16 = 2176 blocks x 256 thr = 557056 threads
#define G1_THREADS (2176*256)

// prep: router blocks then w1-cvt blocks
#define PREP_ROUTER_BLKS (T_TOK/8)          // 1024
#define PREP_CVT_BLKS    (NE*DIM*HID/16/256) // 2048
#define PREP_BLKS (PREP_ROUTER_BLKS + PREP_CVT_BLKS)

// ---------------- device scratch ----------------
__device__ int   g_cnt[NE];
__device__ int   g_tok[NE*T_TOK];
__device__ float g_wt [NE*T_TOK];
__device__ __half g_xh [(size_t)T_TOK*DIM];
__device__ __half g_w1h[(size_t)NE*DIM*HID];
__device__ __half g_w2h[(size_t)NE*HID*DIM];
__device__ __half g_h  [(size_t)MAXROWS*HID];

// ---------------- helpers ----------------
__device__ __forceinline__ float gelu_exact(float v) {
    return 0.5f * v * (1.0f + erff(v * 0.70710678118654752f));
}
__device__ __forceinline__ uint32_t smem_u32(const void* p) {
    uint32_t a; asm("{ .reg .u64 t; cvta.to.shared.u64 t, %1; cvt.u32.u64 %0, t; }" : "=r"(a) : "l"(p));
    return a;
}
__device__ __forceinline__ void cp16(uint32_t d, const void* s) {
    asm volatile("cp.async.cg.shared.global [%0], [%1], 16;" :: "r"(d), "l"(s));
}
#define CP_COMMIT() asm volatile("cp.async.commit_group;" ::: "memory")
#define CP_WAIT1()  asm volatile("cp.async.wait_group 1;" ::: "memory")
#define CP_WAIT0()  asm volatile("cp.async.wait_group 0;" ::: "memory")

#define LDSM4(r, addr) \
    asm volatile("ldmatrix.sync.aligned.m8n8.x4.shared.b16 {%0,%1,%2,%3}, [%4];" \
        : "=r"((r)[0]), "=r"((r)[1]), "=r"((r)[2]), "=r"((r)[3]) : "r"(addr))
#define LDSM4T(r0,r1,r2,r3, addr) \
    asm volatile("ldmatrix.sync.aligned.m8n8.x4.trans.shared.b16 {%0,%1,%2,%3}, [%4];" \
        : "=r"(r0), "=r"(r1), "=r"(r2), "=r"(r3) : "r"(addr))
#define MMA16816(c, a, b) \
    asm volatile("mma.sync.aligned.m16n8k16.row.col.f32.f16.f16.f32 " \
        "{%0,%1,%2,%3}, {%4,%5,%6,%7}, {%8,%9}, {%0,%1,%2,%3};" \
        : "+f"((c)[0]), "+f"((c)[1]), "+f"((c)[2]), "+f"((c)[3]) \
        : "r"((a)[0]), "r"((a)[1]), "r"((a)[2]), "r"((a)[3]), "r"((b)[0]), "r"((b)[1]))

// ---------------- kernel 0: counter reset (must precede router atomics) -----
__global__ void init_cnt_kernel() {
    if (threadIdx.x < NE) g_cnt[threadIdx.x] = 0;
}

// ---------------- kernel 1: prep = router | w1-cvt (independent, no gating) -
__global__ __launch_bounds__(256) void prep_kernel(
    const float* __restrict__ x, const float* __restrict__ rw,
    const float* __restrict__ rb, float* __restrict__ logits_out, int write_logits,
    const float* __restrict__ w1)
{
    int bid = blockIdx.x;
    if (bid < PREP_ROUTER_BLKS) {
        // ---------- router (+ fused x -> fp16) ----------
        __shared__ float sw[NE*DIM];
        __shared__ float sb[NE];
        for (int i = threadIdx.x; i < NE*DIM; i += 256) sw[i] = rw[i];
        if (threadIdx.x < NE) sb[threadIdx.x] = rb[threadIdx.x];
        __syncthreads();

        int warp = threadIdx.x >> 5, lane = threadIdx.x & 31;
        int t = bid * 8 + warp;

        float acc[NE];
#pragma unroll
        for (int e = 0; e < NE; e++) acc[e] = 0.f;

        const float* xr = x + (size_t)t * DIM;
        __half* xh = g_xh + (size_t)t * DIM;
#pragma unroll
        for (int it = 0; it < DIM/64; it++) {
            int d = it*64 + lane*2;
            float2 v = *(const float2*)(xr + d);
            *(__half2*)(xh + d) = __floats2half2_rn(v.x, v.y);
#pragma unroll
            for (int e = 0; e < NE; e++)
                acc[e] += v.x * sw[e*DIM + d] + v.y * sw[e*DIM + d + 1];
        }
#pragma unroll
        for (int e = 0; e < NE; e++) {
#pragma unroll
            for (int off = 16; off > 0; off >>= 1)
                acc[e] += __shfl_xor_sync(0xffffffffu, acc[e], off);
            acc[e] += sb[e];
        }

        if (lane == 0) {
            if (write_logits) {
#pragma unroll
                for (int e = 0; e < NE; e++) logits_out[(size_t)t*NE + e] = acc[e];
            }
            int i0 = 0; float v0 = acc[0];
#pragma unroll
            for (int e = 1; e < NE; e++) if (acc[e] > v0) { v0 = acc[e]; i0 = e; }
            int i1 = -1; float v1 = -1e30f;
#pragma unroll
            for (int e = 0; e < NE; e++) if (e != i0 && acc[e] > v1) { v1 = acc[e]; i1 = e; }
            float ex = expf(v1 - v0);
            float w0 = 1.f / (1.f + ex);
            float w1v = 1.f - w0;

            int s0 = atomicAdd(&g_cnt[i0], 1);
            g_tok[i0*T_TOK + s0] = t; g_wt[i0*T_TOK + s0] = w0;
            int s1 = atomicAdd(&g_cnt[i1], 1);
            g_tok[i1*T_TOK + s1] = t; g_wt[i1*T_TOK + s1] = w1v;
        }
    } else {
        // ---------- w1 -> fp16 convert (MLP=4) ----------
        const int nq = NE*DIM*HID/4/4;   // 524288 quarter-span in float4s
        int i = (bid - PREP_ROUTER_BLKS) * 256 + threadIdx.x;
#pragma unroll
        for (int r = 0; r < 4; r++) {
            int j = i + r*nq;
            float4 a = ((const float4*)w1)[j];
            __half2* d = (__half2*)(g_w1h + (size_t)j*4);
            d[0] = __floats2half2_rn(a.x, a.y);
            d[1] = __floats2half2_rn(a.z, a.w);
        }
    }
}

// ---------------- fp16 pipelined GEMM (128x128x64, 256 thr, 2 CTA/SM) ------
// R11 mainloop (known good). gemm1 additionally hides gemm2's prerequisites
// in its prologue: zero the out token region + convert w2 -> fp16 (DRAM was
// at 4% in gemm1, so this streams under the latency-bound mainloop).
// FIRST:  A = gathered g_xh rows (K=512),  B = g_w1h, out = fp16 gelu(.+b1) -> g_h
// !FIRST: A = g_h rows (K=2048),           B = g_w2h, out: atomicAdd (.+b2)*wt -> out
template<bool FIRST>
__global__ __launch_bounds__(NTHREADS, 2) void moe_gemm_kernel(
    const float* __restrict__ bias, float* __restrict__ out,
    const float* __restrict__ w2src)
{
    constexpr int KEXT = FIRST ? DIM : HID;
    constexpr int NTOT = FIRST ? HID : DIM;
    constexpr int NS   = KEXT / BK;

    int tid = threadIdx.x;

    // ---- gemm1-only side work: zero out-region + cvt w2 (fire-and-forget) --
    if (FIRST) {
        unsigned lid = (blockIdx.y * gridDim.x + blockIdx.x) * NTHREADS + tid;
        // zero out token region: T*DIM/4 = 1048576 float4
        float4 z; z.x = 0.f; z.y = 0.f; z.z = 0.f; z.w = 0.f;
#pragma unroll
        for (int r = 0; r < 2; r++) {
            unsigned j = lid + r * G1_THREADS;
            if (j < (unsigned)(T_TOK*DIM/4)) ((float4*)out)[j] = z;
        }
        // cvt w2: NE*HID*DIM/4 = 2097152 float4; 2 halves of 1048576
        const unsigned nh = NE*HID*DIM/4/2;
#pragma unroll
        for (int r = 0; r < 2; r++) {
            unsigned j = lid + r * G1_THREADS;
            if (j < nh) {
#pragma unroll
                for (int h = 0; h < 2; h++) {
                    unsigned jj = j + h*nh;
                    float4 a = ((const float4*)w2src)[jj];
                    __half2* d = (__half2*)(g_w2h + (size_t)jj*4);
                    d[0] = __floats2half2_rn(a.x, a.y);
                    d[1] = __floats2half2_rn(a.z, a.w);
                }
            }
        }
    }

    // ---- derive (e, slot0, grow0) from g_cnt — no tile table needed ----
    int e, slot0, grow0, cnt;
    {
        int t = blockIdx.x, grow = 0;
        int ee = 0;
#pragma unroll
        for (ee = 0; ee < NE; ee++) {
            int c = __ldg(&g_cnt[ee]);
            int tl = (c + TILE_M - 1) >> 7;
            if (t < tl) break;
            t -= tl; grow += tl * TILE_M;
        }
        if (ee == NE) return;   // beyond last tile
        e = ee; slot0 = t * TILE_M; grow0 = grow + t * TILE_M;
        cnt = __ldg(&g_cnt[e]);
    }
    int n0 = blockIdx.y * BN;

    extern __shared__ char smem[];
    __shared__ float s_wt[BM];
    __shared__ int   s_tok[BM];

    int warp = tid >> 5, lane = tid & 31;
    int wm = warp & 1, wn = warp >> 1;      // 2 x 4 warp grid, 64x32 per warp

    // ---- per-thread source pointers (4 A rows, 4 B chunks) ----
    const __half* aptr[4];
    {
#pragma unroll
        for (int it = 0; it < 4; it++) {
            int row = (tid >> 3) + it*32;
            if (FIRST) {
                int sl = slot0 + row;
                int tok = (sl < cnt) ? g_tok[e*T_TOK + sl] : 0;
                aptr[it] = g_xh + (size_t)tok*DIM + (tid & 7)*8;
            } else {
                aptr[it] = g_h + (size_t)(grow0 + row)*HID + (tid & 7)*8;
            }
        }
        if (!FIRST && tid < BM) {
            int sl = slot0 + tid;
            bool valid = sl < cnt;
            s_wt[tid]  = valid ? g_wt[e*T_TOK + sl] : 0.f;
            s_tok[tid] = valid ? g_tok[e*T_TOK + sl] : -1;
        }
    }
    const __half* Wbase = (FIRST ? g_w1h : g_w2h) + (size_t)e*KEXT*NTOT + n0;

    uint32_t sm_u = smem_u32(smem);
    uint32_t a_dst[4], b_dst[4];
    const __half* bsrc[4];
    {
        int c = tid & 7, row0 = tid >> 3;
#pragma unroll
        for (int it = 0; it < 4; it++) {
            int row = row0 + it*32;
            a_dst[it] = row*128 + ((c ^ (row & 7))*16);
        }
        int bc = tid & 15, k0 = tid >> 4;   // 16 chunks of 16B = 256B per B row
#pragma unroll
        for (int it = 0; it < 4; it++) {
            int k = k0 + it*16;
            b_dst[it] = A_BYTES + k*256 + (((bc ^ (k & 7)) & 15)*16);
            bsrc[it]  = Wbase + (size_t)k*NTOT + bc*8;
        }
    }

    float c[4][4][4];
#pragma unroll
    for (int mf = 0; mf < 4; mf++)
#pragma unroll
        for (int nf = 0; nf < 4; nf++)
#pragma unroll
            for (int r = 0; r < 4; r++) c[mf][nf][r] = 0.f;

    auto load_stage = [&](int s) {
        uint32_t st = sm_u + (s % NSTAGE)*STAGE_B;
#pragma unroll
        for (int it = 0; it < 4; it++)
            cp16(st + a_dst[it], aptr[it] + s*BK);
#pragma unroll
        for (int it = 0; it < 4; it++)
            cp16(st + b_dst[it], bsrc[it] + (size_t)s*BK*NTOT);
    };

    load_stage(0); CP_COMMIT();
    load_stage(1); CP_COMMIT();

    for (int s = 0; s < NS; s++) {
        CP_WAIT1();
        __syncthreads();

        uint32_t stA = sm_u + (s % NSTAGE)*STAGE_B;
        uint32_t stB = stA + A_BYTES;
#pragma unroll
        for (int ks = 0; ks < BK/16; ks++) {
            // ---- first half of A + B fragments ----
            uint32_t a0[2][4];
#pragma unroll
            for (int mf = 0; mf < 2; mf++) {
                int row = wm*64 + mf*16 + (lane & 15);
                int kc  = ks*16 + (lane >> 4)*8;
                uint32_t ad = stA + row*128 + (((kc >> 3) ^ (row & 7))*16);
                LDSM4(a0[mf], ad);
            }
            uint32_t b[4][2];
#pragma unroll
            for (int p = 0; p < 2; p++) {
                int k = ks*16 + (lane & 15);
                int n = wn*32 + p*16 + (lane >> 4)*8;
                uint32_t bd = stB + k*256 + ((((n >> 3) ^ (k & 7)) & 15)*16);
                uint32_t r0, r1, r2, r3;
                LDSM4T(r0, r1, r2, r3, bd);
                b[2*p  ][0] = r0; b[2*p  ][1] = r1;
                b[2*p+1][0] = r2; b[2*p+1][1] = r3;
            }
            // ---- second half of A loads issued before first MMA batch so
            //      their latency is covered by the 8 MMAs below ----
            uint32_t a1[2][4];
#pragma unroll
            for (int mf = 0; mf < 2; mf++) {
                int row = wm*64 + (mf+2)*16 + (lane & 15);
                int kc  = ks*16 + (lane >> 4)*8;
                uint32_t ad = stA + row*128 + (((kc >> 3) ^ (row & 7))*16);
                LDSM4(a1[mf], ad);
            }
#pragma unroll
            for (int mf = 0; mf < 2; mf++)
#pragma unroll
                for (int nf = 0; nf < 4; nf++)
                    MMA16816(c[mf][nf], a0[mf], b[nf]);

            // spread the async prefetch issue away from the post-barrier burst
            if (ks == 0) {
                if (s + 2 < NS) load_stage(s + 2);
                CP_COMMIT();
            }

#pragma unroll
            for (int mf = 0; mf < 2; mf++)
#pragma unroll
                for (int nf = 0; nf < 4; nf++)
                    MMA16816(c[mf+2][nf], a1[mf], b[nf]);
        }
    }
    CP_WAIT0();

    // ---- epilogue ----
    {
        int g = lane >> 2, tq = lane & 3;
        const float* be = bias + (size_t)e*NTOT + n0;
        float bias0[4], bias1[4];
#pragma unroll
        for (int nf = 0; nf < 4; nf++) {
            int col = wn*32 + nf*8 + tq*2;
            bias0[nf] = be[col];
            bias1[nf] = be[col + 1];
        }
#pragma unroll
        for (int mf = 0; mf < 4; mf++) {
            int r0 = wm*64 + mf*16 + g;
            int r1 = r0 + 8;
            if (FIRST) {
                __half* o0 = g_h + (size_t)(grow0 + r0)*HID + n0;
                __half* o1 = g_h + (size_t)(grow0 + r1)*HID + n0;
#pragma unroll
                for (int nf = 0; nf < 4; nf++) {
                    int col = wn*32 + nf*8 + tq*2;
                    float v0 = gelu_exact(c[mf][nf][0] + bias0[nf]);
                    float v1 = gelu_exact(c[mf][nf][1] + bias1[nf]);
                    float v2 = gelu_exact(c[mf][nf][2] + bias0[nf]);
                    float v3 = gelu_exact(c[mf][nf][3] + bias1[nf]);
                    *(__half2*)(o0 + col) = __floats2half2_rn(v0, v1);
                    *(__half2*)(o1 + col) = __floats2half2_rn(v2, v3);
                }
            } else {
                // direct deterministic scatter: exactly 2 fp32 adds per out elem
                float wt0 = s_wt[r0], wt1 = s_wt[r1];
                int  t0 = s_tok[r0], t1 = s_tok[r1];
                float* o0 = out + (size_t)(t0 < 0 ? 0 : t0)*NTOT + n0;
                float* o1 = out + (size_t)(t1 < 0 ? 0 : t1)*NTOT + n0;
#pragma unroll
                for (int nf = 0; nf < 4; nf++) {
                    int col = wn*32 + nf*8 + tq*2;
                    if (t0 >= 0) {
                        atomicAdd(o0 + col,     (c[mf][nf][0] + bias0[nf]) * wt0);
                        atomicAdd(o0 + col + 1, (c[mf][nf][1] + bias1[nf]) * wt0);
                    }
                    if (t1 >= 0) {
                        atomicAdd(o1 + col,     (c[mf][nf][2] + bias0[nf]) * wt1);
                        atomicAdd(o1 + col + 1, (c[mf][nf][3] + bias1[nf]) * wt1);
                    }
                }
            }
        }
    }
}

// ---------------- host entry ----------------
extern "C" void kernel_launch(void* const* d_in, const int* in_sizes, int n_in,
                              void* d_out, int out_size)
{
    const float* x   = (const float*)d_in[0];
    const float* rw  = (const float*)d_in[1];
    const float* rb  = (const float*)d_in[2];
    const float* w1  = (const float*)d_in[3];
    const float* b1  = (const float*)d_in[4];
    const float* w2  = (const float*)d_in[5];
    const float* b2  = (const float*)d_in[6];
    float* out = (float*)d_out;

    int write_logits = (out_size >= T_TOK*DIM + T_TOK*NE) ? 1 : 0;
    float* logits_out = out + (size_t)T_TOK*DIM;

    cudaFuncSetAttribute(moe_gemm_kernel<true>,
                         cudaFuncAttributeMaxDynamicSharedMemorySize, SM_BYTES);
    cudaFuncSetAttribute(moe_gemm_kernel<false>,
                         cudaFuncAttributeMaxDynamicSharedMemorySize, SM_BYTES);

    init_cnt_kernel<<<1, 32>>>();
    prep_kernel<<<PREP_BLKS, 256>>>(x, rw, rb, logits_out, write_logits, w1);
    moe_gemm_kernel<true ><<<dim3(MAXT, HID/BN), NTHREADS, SM_BYTES>>>(b1, out, w2);
    moe_gemm_kernel<false><<<dim3(MAXT, DIM/BN), NTHREADS, SM_BYTES>>>(b2, out, nullptr);
}